// round 9
// baseline (speedup 1.0000x reference)
#include <cuda_runtime.h>
#include <cuda_bf16.h>

#define GNN_NODES 100000
#define D_DIM 256
#define T_LEN 4096
#define B_SZ  64

#define SIM_GRID 1184                    // 148 SMs x 8 resident blocks: ONE wave
#define NCHUNK (B_SZ * (T_LEN / 8))      // 32768 chunks; chunk = 8 t's of one b

// x[b,e] scratch (no cudaMalloc allowed); read back as float4.
__device__ __align__(16) float g_xvec[B_SZ * D_DIM];

// ---------------------------------------------------------------------------
// Prep: 256 blocks. Block (b, q) with b = bid>>2, q = bid&3 computes
// e in [q*64, q*64+64) of x[b,:] = W0 @ g + b0. Fully unrolled matvec
// (16 independent LDG.128 per thread in flight).
// ---------------------------------------------------------------------------
__global__ __launch_bounds__(256) void prep_kernel(
    const int*   __restrict__ batch_nodes,   // [B,T] int32
    const int*   __restrict__ exe,           // [B,T] int32
    const float* __restrict__ graph_dict,    // [GNN,D]
    const float* __restrict__ W0,            // [D,D]
    const float* __restrict__ b0,            // [D]
    float*       __restrict__ gate_out)      // [B]
{
    const int bid  = blockIdx.x;
    const int b    = bid >> 2;
    const int q    = bid & 3;
    const int tid  = threadIdx.x;
    const int wid  = tid >> 5;
    const int lane = tid & 31;

    __shared__ int s_red[256];
    __shared__ int s_doc;
    __shared__ __align__(16) float s_g[D_DIM];

    // last occurrence of 1 in exe[b,:]
    int best = -1;
    const int* er = exe + (size_t)b * T_LEN;
    #pragma unroll 16
    for (int t = tid; t < T_LEN; t += 256)
        if (er[t] == 1) best = t;                 // t increasing, last wins
    s_red[tid] = best;
    __syncthreads();
    for (int off = 128; off > 0; off >>= 1) {
        if (tid < off) s_red[tid] = max(s_red[tid], s_red[tid + off]);
        __syncthreads();
    }
    if (tid == 0) {
        s_doc = s_red[0];
        if (q == 0) gate_out[b] = (s_red[0] >= 0) ? 1.0f : 0.0f;
    }
    __syncthreads();

    // gather g (zeros if none -> x = b0, matching reference)
    const int doc = s_doc;
    if (doc >= 0) {
        int node = batch_nodes[(size_t)b * T_LEN + doc];
        node = min(max(node, 0), GNN_NODES - 1);   // never fault
        s_g[tid] = graph_dict[(size_t)node * D_DIM + tid];
    } else {
        s_g[tid] = 0.0f;
    }
    __syncthreads();

    // matvec: warp w handles e = q*64 + w*8 .. +7, fully unrolled
    const float4* gs4 = reinterpret_cast<const float4*>(s_g);
    const float4  ga  = gs4[lane];
    const float4  gb  = gs4[32 + lane];
    const int e_base = q * 64 + wid * 8;
    #pragma unroll
    for (int i = 0; i < 8; i++) {
        const int e = e_base + i;
        const float4* w4 = reinterpret_cast<const float4*>(W0 + (size_t)e * D_DIM);
        float4 wa = w4[lane];
        float4 wb = w4[32 + lane];
        float s = wa.x*ga.x + wa.y*ga.y + wa.z*ga.z + wa.w*ga.w
                + wb.x*gb.x + wb.y*gb.y + wb.z*gb.z + wb.w*gb.w;
        #pragma unroll
        for (int off = 16; off > 0; off >>= 1)
            s += __shfl_xor_sync(0xffffffffu, s, off);
        if (lane == 0)
            g_xvec[b * D_DIM + e] = s + b0[e];
    }
}

// ---------------------------------------------------------------------------
// Sim (persistent, ONE exact wave of 1184 blocks, <=32 regs, no smem):
// cos[b,t] = (1/sqrt(D)) * dot(x[b,:], src[t,b,:]).
// Work = 32768 chunks (8 t's each) split near-perfectly across blocks
// (max imbalance 1 chunk ~ 0.3%) -> no wave-quantization tail.
// ---------------------------------------------------------------------------
__global__ __launch_bounds__(256, 8) void sim_kernel(
    const float* __restrict__ src,     // [T,B,D]
    float*       __restrict__ cos_out) // [B,T]
{
    const int j    = blockIdx.x;
    const int wid  = threadIdx.x >> 5;
    const int lane = threadIdx.x & 31;

    const int c0 = (int)(((long long)NCHUNK * j)       / SIM_GRID);
    const int c1 = (int)(((long long)NCHUNK * (j + 1)) / SIM_GRID);

    const float scale = 0.0625f;  // 1/sqrt(256)
    int    cur_b = -1;
    float4 xa, xb;

    for (int c = c0 + wid; c < c1; c += 8) {
        const int b = c >> 9;                  // 512 chunks per b
        if (b != cur_b) {
            const float4* xg = reinterpret_cast<const float4*>(g_xvec + b * D_DIM);
            xa = xg[lane];
            xb = xg[32 + lane];
            cur_b = b;
        }
        const int t0 = (c & 511) << 3;

        const float4* p = reinterpret_cast<const float4*>(
            src + ((size_t)t0 * B_SZ + b) * D_DIM);
        float* o = cos_out + (size_t)b * T_LEN + t0;

        #pragma unroll
        for (int i = 0; i < 8; i++) {
            float4 a = p[lane];
            float4 cc = p[32 + lane];
            float v = a.x*xa.x + a.y*xa.y + a.z*xa.z + a.w*xa.w
                    + cc.x*xb.x + cc.y*xb.y + cc.z*xb.z + cc.w*xb.w;
            #pragma unroll
            for (int off = 16; off > 0; off >>= 1)
                v += __shfl_xor_sync(0xffffffffu, v, off);
            if (lane == 0) o[i] = v * scale;
            p += (size_t)B_SZ * D_DIM / 4;     // next t: +64KB
        }
    }
}

extern "C" void kernel_launch(void* const* d_in, const int* in_sizes, int n_in,
                              void* d_out, int out_size)
{
    const int*   batch_nodes = (const int*)d_in[0];   // [B,T] int32
    const int*   exe         = (const int*)d_in[1];   // [B,T] int32
    const float* src         = (const float*)d_in[2]; // [T,B,D]
    const float* graph_dict  = (const float*)d_in[3]; // [GNN,D]
    const float* W0          = (const float*)d_in[4]; // [D,D]
    const float* b0          = (const float*)d_in[5]; // [D]

    float* out  = (float*)d_out;
    float* cos  = out;                        // [B,T]
    float* gate = out + (size_t)B_SZ * T_LEN; // [B]

    prep_kernel<<<256, 256>>>(batch_nodes, exe, graph_dict, W0, b0, gate);

    sim_kernel<<<SIM_GRID, 256>>>(src, cos);
}

// round 10
// speedup vs baseline: 1.0310x; 1.0310x over previous
#include <cuda_runtime.h>
#include <cuda_bf16.h>

#define GNN_NODES 100000
#define D_DIM 256
#define T_LEN 4096
#define B_SZ  64

// x[b,e] scratch (no cudaMalloc allowed); read back as float4.
__device__ __align__(16) float g_xvec[B_SZ * D_DIM];

// ---------------------------------------------------------------------------
// Prep: 256 blocks. Block (b, q) with b = bid>>2, q = bid&3 computes
// e in [q*64, q*64+64) of x[b,:] = W0 @ g + b0. Fully unrolled matvec
// (16 independent LDG.128 per thread in flight).
// ---------------------------------------------------------------------------
__global__ __launch_bounds__(256) void prep_kernel(
    const int*   __restrict__ batch_nodes,   // [B,T] int32
    const int*   __restrict__ exe,           // [B,T] int32
    const float* __restrict__ graph_dict,    // [GNN,D]
    const float* __restrict__ W0,            // [D,D]
    const float* __restrict__ b0,            // [D]
    float*       __restrict__ gate_out)      // [B]
{
    const int bid  = blockIdx.x;
    const int b    = bid >> 2;
    const int q    = bid & 3;
    const int tid  = threadIdx.x;
    const int wid  = tid >> 5;
    const int lane = tid & 31;

    __shared__ int s_red[256];
    __shared__ int s_doc;
    __shared__ __align__(16) float s_g[D_DIM];

    // last occurrence of 1 in exe[b,:]
    int best = -1;
    const int* er = exe + (size_t)b * T_LEN;
    #pragma unroll 16
    for (int t = tid; t < T_LEN; t += 256)
        if (er[t] == 1) best = t;                 // t increasing, last wins
    s_red[tid] = best;
    __syncthreads();
    for (int off = 128; off > 0; off >>= 1) {
        if (tid < off) s_red[tid] = max(s_red[tid], s_red[tid + off]);
        __syncthreads();
    }
    if (tid == 0) {
        s_doc = s_red[0];
        if (q == 0) gate_out[b] = (s_red[0] >= 0) ? 1.0f : 0.0f;
    }
    __syncthreads();

    // gather g (zeros if none -> x = b0, matching reference)
    const int doc = s_doc;
    if (doc >= 0) {
        int node = batch_nodes[(size_t)b * T_LEN + doc];
        node = min(max(node, 0), GNN_NODES - 1);   // never fault
        s_g[tid] = graph_dict[(size_t)node * D_DIM + tid];
    } else {
        s_g[tid] = 0.0f;
    }
    __syncthreads();

    // matvec: warp w handles e = q*64 + w*8 .. +7, fully unrolled
    const float4* gs4 = reinterpret_cast<const float4*>(s_g);
    const float4  ga  = gs4[lane];
    const float4  gb  = gs4[32 + lane];
    const int e_base = q * 64 + wid * 8;
    #pragma unroll
    for (int i = 0; i < 8; i++) {
        const int e = e_base + i;
        const float4* w4 = reinterpret_cast<const float4*>(W0 + (size_t)e * D_DIM);
        float4 wa = w4[lane];
        float4 wb = w4[32 + lane];
        float s = wa.x*ga.x + wa.y*ga.y + wa.z*ga.z + wa.w*ga.w
                + wb.x*gb.x + wb.y*gb.y + wb.z*gb.z + wb.w*gb.w;
        #pragma unroll
        for (int off = 16; off > 0; off >>= 1)
            s += __shfl_xor_sync(0xffffffffu, s, off);
        if (lane == 0)
            g_xvec[b * D_DIM + e] = s + b0[e];
    }
}

// ---------------------------------------------------------------------------
// Sim: cos[b,t] = (1/sqrt(D)) * dot(x[b,:], src[t,b,:]).
// R8 structure (32 regs, no smem, HW-scheduled small blocks) but block = 32 t
// -> 8192 blocks = 6.92 work-waves over 1184 slots -> 98.9% wave efficiency
// (vs 86.5% at 64 t/block). Warp walks 4 consecutive t's of one b.
// ---------------------------------------------------------------------------
__global__ __launch_bounds__(256, 8) void sim_kernel(
    const float* __restrict__ src,     // [T,B,D]
    float*       __restrict__ cos_out) // [B,T]
{
    const int b    = blockIdx.y;
    const int lane = threadIdx.x & 31;
    const int t0   = blockIdx.x * 32 + (threadIdx.x >> 5) * 4;

    // x straight from global (L2-hot after prep kernel)
    const float4* xg = reinterpret_cast<const float4*>(g_xvec + b * D_DIM);
    const float4 xa = xg[lane];
    const float4 xb = xg[32 + lane];

    const float4* p = reinterpret_cast<const float4*>(
        src + ((size_t)t0 * B_SZ + b) * D_DIM);
    float* o = cos_out + (size_t)b * T_LEN + t0;

    const float scale = 0.0625f;  // 1/sqrt(256)

    #pragma unroll
    for (int i = 0; i < 4; i++) {
        float4 a = p[lane];
        float4 c = p[32 + lane];
        float v = a.x*xa.x + a.y*xa.y + a.z*xa.z + a.w*xa.w
                + c.x*xb.x + c.y*xb.y + c.z*xb.z + c.w*xb.w;
        #pragma unroll
        for (int off = 16; off > 0; off >>= 1)
            v += __shfl_xor_sync(0xffffffffu, v, off);
        if (lane == 0) o[i] = v * scale;
        p += (size_t)B_SZ * D_DIM / 4;   // next t: +64KB
    }
}

extern "C" void kernel_launch(void* const* d_in, const int* in_sizes, int n_in,
                              void* d_out, int out_size)
{
    const int*   batch_nodes = (const int*)d_in[0];   // [B,T] int32
    const int*   exe         = (const int*)d_in[1];   // [B,T] int32
    const float* src         = (const float*)d_in[2]; // [T,B,D]
    const float* graph_dict  = (const float*)d_in[3]; // [GNN,D]
    const float* W0          = (const float*)d_in[4]; // [D,D]
    const float* b0          = (const float*)d_in[5]; // [D]

    float* out  = (float*)d_out;
    float* cos  = out;                        // [B,T]
    float* gate = out + (size_t)B_SZ * T_LEN; // [B]

    prep_kernel<<<256, 256>>>(batch_nodes, exe, graph_dict, W0, b0, gate);

    dim3 grid(T_LEN / 32, B_SZ);   // 128 x 64 = 8192 blocks
    sim_kernel<<<grid, 256>>>(src, cos);
}